// round 1
// baseline (speedup 1.0000x reference)
#include <cuda_runtime.h>

#define Nn    6144
#define EMB   256
#define HID   128
#define EPOS  98304
#define ENEG  24576
#define EPOT  262144
#define SIGMA 100.0f
#define TDEL  0.1f

// scratch: latent_link (branch 0) and latent_aa (branch 1), plus loss accumulator
__device__ float g_latent[2][Nn * HID];
__device__ float g_loss;

// ---------------------------------------------------------------------------
// Fused 2-layer MLP: out = relu(emb @ W1 + b1) @ W2 + b2
// 32 rows per block, 256 threads. blockIdx.y selects branch (link / aa).
// ---------------------------------------------------------------------------
__global__ __launch_bounds__(256) void mlp_kernel(
    const float* __restrict__ emb,
    const float* __restrict__ W1l, const float* __restrict__ b1l,
    const float* __restrict__ W2l, const float* __restrict__ b2l,
    const float* __restrict__ W1a, const float* __restrict__ b1a,
    const float* __restrict__ W2a, const float* __restrict__ b2a)
{
    __shared__ float sE[32 * EMB];   // 32 KB
    __shared__ float sH[32 * HID];   // 16 KB

    const int branch = blockIdx.y;
    const float* W1 = branch ? W1a : W1l;
    const float* b1 = branch ? b1a : b1l;
    const float* W2 = branch ? W2a : W2l;
    const float* b2 = branch ? b2a : b2l;
    float* out = g_latent[branch];

    const int r0  = blockIdx.x * 32;
    const int tid = threadIdx.x;

    if (blockIdx.x == 0 && branch == 0 && tid == 0) g_loss = 0.0f;

    // load emb tile (32 x 256 floats, contiguous) via float4
    {
        const float4* src = (const float4*)(emb + (size_t)r0 * EMB);
        float4* dst = (float4*)sE;
        #pragma unroll
        for (int i = 0; i < 8; i++) dst[tid + i * 256] = src[tid + i * 256];
    }
    __syncthreads();

    const int c0 = (tid & 63) * 2;   // column pair 0..126
    const int rh = tid >> 6;         // row phase 0..3

    float acc[8][2];

    // ---- stage 1: H = relu(emb @ W1 + b1) ----
    #pragma unroll
    for (int m = 0; m < 8; m++) { acc[m][0] = b1[c0]; acc[m][1] = b1[c0 + 1]; }

    for (int k = 0; k < EMB; k++) {
        float2 w = *(const float2*)(W1 + k * HID + c0);
        #pragma unroll
        for (int m = 0; m < 8; m++) {
            float e = sE[(rh + m * 4) * EMB + k];   // broadcast within warp
            acc[m][0] += e * w.x;
            acc[m][1] += e * w.y;
        }
    }
    #pragma unroll
    for (int m = 0; m < 8; m++) {
        float2 h;
        h.x = fmaxf(acc[m][0], 0.0f);
        h.y = fmaxf(acc[m][1], 0.0f);
        *(float2*)(sH + (rh + m * 4) * HID + c0) = h;
    }
    __syncthreads();

    // ---- stage 2: out = H @ W2 + b2 ----
    #pragma unroll
    for (int m = 0; m < 8; m++) { acc[m][0] = b2[c0]; acc[m][1] = b2[c0 + 1]; }

    for (int k = 0; k < HID; k++) {
        float2 w = *(const float2*)(W2 + k * HID + c0);
        #pragma unroll
        for (int m = 0; m < 8; m++) {
            float h = sH[(rh + m * 4) * HID + k];
            acc[m][0] += h * w.x;
            acc[m][1] += h * w.y;
        }
    }
    #pragma unroll
    for (int m = 0; m < 8; m++) {
        int r = r0 + rh + m * 4;
        float2 o; o.x = acc[m][0]; o.y = acc[m][1];
        *(float2*)(out + r * HID + c0) = o;
    }
}

// ---------------------------------------------------------------------------
// Edge kernel: one warp per (i,j) pair. Edge id space:
//   [0, ENEG)                -> negative edges (loss)
//   [ENEG, ENEG+EPOS)        -> positive edges (loss)
//   [ENEG+EPOS, TOT)         -> potential edges (pre_weights output)
// ---------------------------------------------------------------------------
__device__ __forceinline__ float fsigmoid(float x) {
    return 1.0f / (1.0f + __expf(-x));
}

__global__ __launch_bounds__(256) void edge_kernel(
    const float* __restrict__ aa,
    const float* __restrict__ fdiff,
    const int*   __restrict__ pos_e,
    const int*   __restrict__ neg_e,
    const int*   __restrict__ pot_e,
    const float* __restrict__ emb_w,
    const float* __restrict__ struct_w,
    float* __restrict__ out)
{
    __shared__ float part[8];

    const int warp = (blockIdx.x * 256 + threadIdx.x) >> 5;
    const int lane = threadIdx.x & 31;
    const int wib  = threadIdx.x >> 5;

    int i, j, kind, le;
    if (warp < ENEG) {
        le = warp; i = neg_e[le]; j = neg_e[ENEG + le]; kind = 0;
    } else if (warp < ENEG + EPOS) {
        le = warp - ENEG; i = pos_e[le]; j = pos_e[EPOS + le]; kind = 1;
    } else {
        le = warp - ENEG - EPOS; i = pot_e[le]; j = pot_e[EPOT + le]; kind = 2;
    }

    // 128-dim dot products; each lane owns one float4 of the row
    const float4* Li = (const float4*)(g_latent[0] + i * HID);
    const float4* Lj = (const float4*)(g_latent[0] + j * HID);
    const float4* Ai = (const float4*)(g_latent[1] + i * HID);
    const float4* Aj = (const float4*)(g_latent[1] + j * HID);

    float4 a = Li[lane], b = Lj[lane];
    float d1 = a.x * b.x + a.y * b.y + a.z * b.z + a.w * b.w;
    float4 c = Ai[lane], d = Aj[lane];
    float d2 = c.x * d.x + c.y * d.y + c.z * d.z + c.w * d.w;

    #pragma unroll
    for (int s = 16; s; s >>= 1) {
        d1 += __shfl_xor_sync(0xffffffffu, d1, s);
        d2 += __shfl_xor_sync(0xffffffffu, d2, s);
    }

    if (lane == 0) {
        float contrib = 0.0f;
        float aval = aa[i * Nn + j];
        float ew = emb_w[0], sw = struct_w[0];
        float lc = fsigmoid(d1);
        float ac = fsigmoid(d2 * aval);
        float v  = fsigmoid(ew * lc + sw * ac);
        if (kind == 2) {
            out[1 + le] = (v < TDEL) ? 0.0f : v;
        } else {
            float fd = fdiff[i * Nn + j] * (1.0f / SIGMA);
            float q = fd * fd;
            if (kind == 1) {
                float e1 = v - 1.0f;
                contrib = __expf(-q) * e1 * e1;
            } else {
                contrib = __expf(q) * v * v;
            }
        }
        part[wib] = contrib;
    }
    __syncthreads();

    if (threadIdx.x == 0) {
        float s = part[0] + part[1] + part[2] + part[3]
                + part[4] + part[5] + part[6] + part[7];
        if (s != 0.0f) atomicAdd(&g_loss, s);
    }
}

__global__ void finalize_kernel(float* __restrict__ out) {
    if (threadIdx.x == 0)
        out[0] = g_loss * ((float)Nn / (float)(ENEG + EPOS));
}

// ---------------------------------------------------------------------------
extern "C" void kernel_launch(void* const* d_in, const int* in_sizes, int n_in,
                              void* d_out, int out_size)
{
    const float* emb   = (const float*)d_in[0];
    const float* aa    = (const float*)d_in[1];
    const float* fdiff = (const float*)d_in[2];
    const float* W1l   = (const float*)d_in[3];
    const float* b1l   = (const float*)d_in[4];
    const float* W2l   = (const float*)d_in[5];
    const float* b2l   = (const float*)d_in[6];
    const float* W1a   = (const float*)d_in[7];
    const float* b1a   = (const float*)d_in[8];
    const float* W2a   = (const float*)d_in[9];
    const float* b2a   = (const float*)d_in[10];
    const float* emw   = (const float*)d_in[11];
    const float* stw   = (const float*)d_in[12];
    const int*   pose  = (const int*)d_in[13];
    const int*   nege  = (const int*)d_in[14];
    const int*   pote  = (const int*)d_in[15];
    float* out = (float*)d_out;

    dim3 mgrid(Nn / 32, 2);
    mlp_kernel<<<mgrid, 256>>>(emb, W1l, b1l, W2l, b2l, W1a, b1a, W2a, b2a);

    const int TOT = ENEG + EPOS + EPOT;          // 385024
    edge_kernel<<<TOT / 8, 256>>>(aa, fdiff, pose, nege, pote, emw, stw, out);

    finalize_kernel<<<1, 32>>>(out);
}

// round 3
// speedup vs baseline: 1.0775x; 1.0775x over previous
#include <cuda_runtime.h>
#include <cuda_fp16.h>

#define Nn    6144
#define EMB   256
#define HID   128
#define EPOS  98304
#define ENEG  24576
#define EPOT  262144
#define SIGMA 100.0f
#define TDEL  0.1f

#define NEG_BLKS  (ENEG / 8)            // 3072
#define POSNEG_BLKS ((ENEG + EPOS) / 8) // 15360

typedef unsigned long long u64;

// latents: per node [link 0..127 | aa 128..255] halves = 512B per node
__device__ __half g_lat[Nn * 256];
// spread loss accumulators (128B stride)
__device__ float g_loss[64 * 32];

__device__ __forceinline__ u64 pack2(float lo, float hi) {
    u64 r; asm("mov.b64 %0, {%1,%2};" : "=l"(r) : "f"(lo), "f"(hi)); return r;
}
__device__ __forceinline__ void unpack2(u64 v, float& lo, float& hi) {
    asm("mov.b64 {%0,%1}, %2;" : "=f"(lo), "=f"(hi) : "l"(v));
}
__device__ __forceinline__ u64 ffma2(u64 a, u64 b, u64 c) {
    u64 d; asm("fma.rn.f32x2 %0, %1, %2, %3;" : "=l"(d) : "l"(a), "l"(b), "l"(c));
    return d;
}

// ---------------------------------------------------------------------------
// Fused 2-layer MLP with packed f32x2 FMA.
// Block: 32 rows x 128 cols, 256 threads. Thread: 4 rows x 4 cols.
// warp == rid, so emb / sH row reads are uniform broadcasts.
// ---------------------------------------------------------------------------
__global__ __launch_bounds__(256, 3) void mlp_kernel(
    const float* __restrict__ emb,
    const float* __restrict__ W1l, const float* __restrict__ b1l,
    const float* __restrict__ W2l, const float* __restrict__ b2l,
    const float* __restrict__ W1a, const float* __restrict__ b1a,
    const float* __restrict__ W2a, const float* __restrict__ b2a)
{
    __shared__ float sH[32 * HID];   // 16 KB

    const int branch = blockIdx.y;
    const float* W1 = branch ? W1a : W1l;
    const float* b1 = branch ? b1a : b1l;
    const float* W2 = branch ? W2a : W2l;
    const float* b2 = branch ? b2a : b2l;

    const int r0  = blockIdx.x * 32;
    const int tid = threadIdx.x;
    const int cid = tid & 31;
    const int c0  = cid * 4;
    const int rid = tid >> 5;        // == warp id

    if (blockIdx.x == 0 && branch == 0 && tid < 64) g_loss[tid * 32] = 0.0f;

    const float* erow0 = emb + (size_t)(r0 + rid) * EMB;

    u64 acc[4][2];

    // ---- stage 1: H = relu(emb @ W1 + b1) ----
    {
        float4 bv = *(const float4*)(b1 + c0);
        #pragma unroll
        for (int m = 0; m < 4; m++) {
            acc[m][0] = pack2(bv.x, bv.y);
            acc[m][1] = pack2(bv.z, bv.w);
        }
    }
    for (int k = 0; k < EMB; k += 4) {
        u64 wp[4][2];
        #pragma unroll
        for (int t = 0; t < 4; t++) {
            float4 w = *(const float4*)(W1 + (k + t) * HID + c0);
            wp[t][0] = pack2(w.x, w.y);
            wp[t][1] = pack2(w.z, w.w);
        }
        #pragma unroll
        for (int m = 0; m < 4; m++) {
            float4 e = *(const float4*)(erow0 + m * 8 * EMB + k);
            u64 e0 = pack2(e.x, e.x), e1 = pack2(e.y, e.y);
            u64 e2 = pack2(e.z, e.z), e3 = pack2(e.w, e.w);
            acc[m][0] = ffma2(e0, wp[0][0], acc[m][0]);
            acc[m][1] = ffma2(e0, wp[0][1], acc[m][1]);
            acc[m][0] = ffma2(e1, wp[1][0], acc[m][0]);
            acc[m][1] = ffma2(e1, wp[1][1], acc[m][1]);
            acc[m][0] = ffma2(e2, wp[2][0], acc[m][0]);
            acc[m][1] = ffma2(e2, wp[2][1], acc[m][1]);
            acc[m][0] = ffma2(e3, wp[3][0], acc[m][0]);
            acc[m][1] = ffma2(e3, wp[3][1], acc[m][1]);
        }
    }
    #pragma unroll
    for (int m = 0; m < 4; m++) {
        float f0, f1, f2, f3;
        unpack2(acc[m][0], f0, f1);
        unpack2(acc[m][1], f2, f3);
        float4 h;
        h.x = fmaxf(f0, 0.0f); h.y = fmaxf(f1, 0.0f);
        h.z = fmaxf(f2, 0.0f); h.w = fmaxf(f3, 0.0f);
        *(float4*)(sH + (rid + m * 8) * HID + c0) = h;
    }
    __syncthreads();

    // ---- stage 2: out = H @ W2 + b2 ----
    {
        float4 bv = *(const float4*)(b2 + c0);
        #pragma unroll
        for (int m = 0; m < 4; m++) {
            acc[m][0] = pack2(bv.x, bv.y);
            acc[m][1] = pack2(bv.z, bv.w);
        }
    }
    for (int k = 0; k < HID; k += 4) {
        u64 wp[4][2];
        #pragma unroll
        for (int t = 0; t < 4; t++) {
            float4 w = *(const float4*)(W2 + (k + t) * HID + c0);
            wp[t][0] = pack2(w.x, w.y);
            wp[t][1] = pack2(w.z, w.w);
        }
        #pragma unroll
        for (int m = 0; m < 4; m++) {
            float4 e = *(const float4*)(sH + (rid + m * 8) * HID + k);
            u64 e0 = pack2(e.x, e.x), e1 = pack2(e.y, e.y);
            u64 e2 = pack2(e.z, e.z), e3 = pack2(e.w, e.w);
            acc[m][0] = ffma2(e0, wp[0][0], acc[m][0]);
            acc[m][1] = ffma2(e0, wp[0][1], acc[m][1]);
            acc[m][0] = ffma2(e1, wp[1][0], acc[m][0]);
            acc[m][1] = ffma2(e1, wp[1][1], acc[m][1]);
            acc[m][0] = ffma2(e2, wp[2][0], acc[m][0]);
            acc[m][1] = ffma2(e2, wp[2][1], acc[m][1]);
            acc[m][0] = ffma2(e3, wp[3][0], acc[m][0]);
            acc[m][1] = ffma2(e3, wp[3][1], acc[m][1]);
        }
    }
    // store fp16 latents: node-major [link | aa]
    #pragma unroll
    for (int m = 0; m < 4; m++) {
        float f0, f1, f2, f3;
        unpack2(acc[m][0], f0, f1);
        unpack2(acc[m][1], f2, f3);
        __half2 h01 = __floats2half2_rn(f0, f1);
        __half2 h23 = __floats2half2_rn(f2, f3);
        int r = r0 + rid + m * 8;
        uint2 st;
        st.x = *(unsigned int*)&h01;
        st.y = *(unsigned int*)&h23;
        *(uint2*)(g_lat + r * 256 + branch * 128 + c0) = st;
    }
}

// ---------------------------------------------------------------------------
// Edge kernel: one warp per (i,j) pair, 8 edges per block.
// Blocks are kind-homogeneous: [0,3072) neg, [3072,15360) pos, rest pot.
// Lanes 0-15 accumulate the link dot, lanes 16-31 the aa dot.
// ---------------------------------------------------------------------------
__device__ __forceinline__ float fsigmoid(float x) {
    return 1.0f / (1.0f + __expf(-x));
}

__global__ __launch_bounds__(256) void edge_kernel(
    const float* __restrict__ aa,
    const float* __restrict__ fdiff,
    const int*   __restrict__ pos_e,
    const int*   __restrict__ neg_e,
    const int*   __restrict__ pot_e,
    const float* __restrict__ emb_w,
    const float* __restrict__ struct_w,
    float* __restrict__ out)
{
    __shared__ float sv[8];

    const int b    = blockIdx.x;
    const int wib  = threadIdx.x >> 5;
    const int lane = threadIdx.x & 31;
    const int gw   = b * 8 + wib;

    int i, j;
    if (b < NEG_BLKS) {
        i = neg_e[gw]; j = neg_e[ENEG + gw];
    } else if (b < POSNEG_BLKS) {
        int le = gw - ENEG;
        i = pos_e[le]; j = pos_e[EPOS + le];
    } else {
        int le = gw - (ENEG + EPOS);
        i = pot_e[le]; j = pot_e[EPOT + le];
    }

    // each lane: 8 halves (16B) of the combined [link|aa] node row
    const uint4 u = *((const uint4*)(g_lat + i * 256) + lane);
    const uint4 v = *((const uint4*)(g_lat + j * 256) + lane);

    float d = 0.0f;
    {
        float2 a, c;
        a = __half22float2(*(const __half2*)&u.x); c = __half22float2(*(const __half2*)&v.x);
        d += a.x * c.x + a.y * c.y;
        a = __half22float2(*(const __half2*)&u.y); c = __half22float2(*(const __half2*)&v.y);
        d += a.x * c.x + a.y * c.y;
        a = __half22float2(*(const __half2*)&u.z); c = __half22float2(*(const __half2*)&v.z);
        d += a.x * c.x + a.y * c.y;
        a = __half22float2(*(const __half2*)&u.w); c = __half22float2(*(const __half2*)&v.w);
        d += a.x * c.x + a.y * c.y;
    }
    // butterfly within each 16-lane half
    #pragma unroll
    for (int s = 8; s; s >>= 1)
        d += __shfl_xor_sync(0xffffffffu, d, s);
    // cross half: lane 0 gets the aa-dot from lane 16
    float dother = __shfl_xor_sync(0xffffffffu, d, 16);

    if (lane == 0) {
        float d1 = d, d2 = dother;
        float aval = __ldg(aa + (size_t)i * Nn + j);
        float ew = emb_w[0], sw = struct_w[0];
        float lc = fsigmoid(d1);
        float ac = fsigmoid(d2 * aval);
        float vv = fsigmoid(ew * lc + sw * ac);
        if (b >= POSNEG_BLKS) {
            sv[wib] = (vv < TDEL) ? 0.0f : vv;
        } else {
            float fd = __ldg(fdiff + (size_t)i * Nn + j) * (1.0f / SIGMA);
            float q = fd * fd;
            if (b >= NEG_BLKS) {             // positive edge
                float e1 = vv - 1.0f;
                sv[wib] = __expf(-q) * e1 * e1;
            } else {                          // negative edge
                sv[wib] = __expf(q) * vv * vv;
            }
        }
    }
    __syncthreads();

    if (b >= POSNEG_BLKS) {
        if (threadIdx.x < 8)
            out[1 + (b - POSNEG_BLKS) * 8 + threadIdx.x] = sv[threadIdx.x];
    } else if (threadIdx.x == 0) {
        float s = sv[0] + sv[1] + sv[2] + sv[3] + sv[4] + sv[5] + sv[6] + sv[7];
        atomicAdd(&g_loss[(b & 63) * 32], s);
    }
}

__global__ void finalize_kernel(float* __restrict__ out) {
    if (threadIdx.x == 0) {
        float s = 0.0f;
        #pragma unroll
        for (int t = 0; t < 64; t++) s += g_loss[t * 32];
        out[0] = s * ((float)Nn / (float)(ENEG + EPOS));
    }
}

// ---------------------------------------------------------------------------
extern "C" void kernel_launch(void* const* d_in, const int* in_sizes, int n_in,
                              void* d_out, int out_size)
{
    const float* emb   = (const float*)d_in[0];
    const float* aa    = (const float*)d_in[1];
    const float* fdiff = (const float*)d_in[2];
    const float* W1l   = (const float*)d_in[3];
    const float* b1l   = (const float*)d_in[4];
    const float* W2l   = (const float*)d_in[5];
    const float* b2l   = (const float*)d_in[6];
    const float* W1a   = (const float*)d_in[7];
    const float* b1a   = (const float*)d_in[8];
    const float* W2a   = (const float*)d_in[9];
    const float* b2a   = (const float*)d_in[10];
    const float* emw   = (const float*)d_in[11];
    const float* stw   = (const float*)d_in[12];
    const int*   pose  = (const int*)d_in[13];
    const int*   nege  = (const int*)d_in[14];
    const int*   pote  = (const int*)d_in[15];
    float* out = (float*)d_out;

    dim3 mgrid(Nn / 32, 2);
    mlp_kernel<<<mgrid, 256>>>(emb, W1l, b1l, W2l, b2l, W1a, b1a, W2a, b2a);

    const int TOT = ENEG + EPOS + EPOT;          // 385024
    edge_kernel<<<TOT / 8, 256>>>(aa, fdiff, pose, nege, pote, emw, stw, out);

    finalize_kernel<<<1, 32>>>(out);
}

// round 4
// speedup vs baseline: 1.2402x; 1.1510x over previous
#include <cuda_runtime.h>
#include <cuda_fp16.h>

#define Nn    6144
#define EMB   256
#define HID   128
#define EPOS  98304
#define ENEG  24576
#define EPOT  262144
#define SIGMA 100.0f
#define TDEL  0.1f

#define NEG_BLKS    (ENEG / 8)            // 3072
#define POSNEG_BLKS ((ENEG + EPOS) / 8)   // 15360

// fp16 staging
__device__ __half hE[Nn * EMB];            // emb, row-major
__device__ __half hW1t[2][HID * EMB];      // n-major: [n*256 + k]
__device__ __half hW2t[2][HID * HID];      // n-major: [n*128 + k]
// latents: per node [link 0..127 | aa 128..255] = 512B
__device__ __half g_lat[Nn * 256];
// spread loss accumulators (128B stride)
__device__ float g_loss[64 * 32];

// ---------------------------------------------------------------------------
// prep: fp32 -> fp16 conversions + weight transpose + loss zeroing
// grid: Nn + 384 blocks of 256 threads
// ---------------------------------------------------------------------------
__global__ __launch_bounds__(256) void prep_kernel(
    const float* __restrict__ emb,
    const float* __restrict__ W1l, const float* __restrict__ W1a,
    const float* __restrict__ W2l, const float* __restrict__ W2a)
{
    const int b = blockIdx.x, tid = threadIdx.x;
    if (b == 0 && tid < 64) g_loss[tid * 32] = 0.0f;
    if (b < Nn) {
        int idx = b * EMB + tid;
        hE[idx] = __float2half(emb[idx]);
    } else {
        int widx = (b - Nn) * 256 + tid;          // [0, 98304)
        if (widx < 2 * EMB * HID) {               // W1 transposes
            int br = widx >> 15;
            int t  = widx & 32767;
            int k  = t >> 7, n = t & 127;
            const float* W = br ? W1a : W1l;
            hW1t[br][n * EMB + k] = __float2half(W[k * HID + n]);
        } else {
            int t2 = widx - 2 * EMB * HID;
            int br = t2 >> 14;
            int t  = t2 & 16383;
            int k  = t >> 7, n = t & 127;
            const float* W = br ? W2a : W2l;
            hW2t[br][n * HID + k] = __float2half(W[k * HID + n]);
        }
    }
}

// ---------------------------------------------------------------------------
// MLP via mma.sync.m16n8k16 (HMMA, fp16 in / fp32 accum).
// Block: 128 threads = 4 warps. Block tile: 64 rows x 128 cols.
//   warp w: rowgroup rg=w&1 (32 rows), colgroup cg=w>>1 (64 cols)
//   per warp: 2 mtiles(16r) x 8 ntiles(8c)
// ---------------------------------------------------------------------------
__device__ __forceinline__ void mma16816(float* c, const unsigned* a,
                                         unsigned b0, unsigned b1) {
    asm volatile(
        "mma.sync.aligned.m16n8k16.row.col.f32.f16.f16.f32 "
        "{%0,%1,%2,%3}, {%4,%5,%6,%7}, {%8,%9}, {%0,%1,%2,%3};"
        : "+f"(c[0]), "+f"(c[1]), "+f"(c[2]), "+f"(c[3])
        : "r"(a[0]), "r"(a[1]), "r"(a[2]), "r"(a[3]), "r"(b0), "r"(b1));
}

#define SH_PITCH 136   // padded half-stride: conflict-free for quad layout

__global__ __launch_bounds__(128) void mlp_kernel(
    const float* __restrict__ b1l, const float* __restrict__ b2l,
    const float* __restrict__ b1a, const float* __restrict__ b2a)
{
    __shared__ __half sH[64 * SH_PITCH];   // 17408 B

    const int branch = blockIdx.y;
    const float* B1 = branch ? b1a : b1l;
    const float* B2 = branch ? b2a : b2l;
    const __half* W1 = hW1t[branch];
    const __half* W2 = hW2t[branch];

    const int tid  = threadIdx.x;
    const int w    = tid >> 5;
    const int lane = tid & 31;
    const int rg   = w & 1;          // rowgroup
    const int cg   = w >> 1;         // colgroup
    const int r    = lane >> 2;      // 0..7
    const int c2   = (lane & 3) * 2; // 0,2,4,6

    const int R0 = blockIdx.x * 64 + rg * 32;  // global row base for warp
    const int C0 = cg * 64;                    // col base

    float acc[2][8][4];
    #pragma unroll
    for (int m = 0; m < 2; m++)
        #pragma unroll
        for (int n = 0; n < 8; n++)
            #pragma unroll
            for (int q = 0; q < 4; q++) acc[m][n][q] = 0.0f;

    // ---- stage 1: acc = emb @ W1 ----
    #pragma unroll 4
    for (int kt = 0; kt < EMB / 16; kt++) {
        const int k0 = kt * 16;
        unsigned a[2][4];
        #pragma unroll
        for (int m = 0; m < 2; m++) {
            const __half* Ab = hE + (size_t)(R0 + m * 16 + r) * EMB + k0 + c2;
            a[m][0] = *(const unsigned*)Ab;
            a[m][1] = *(const unsigned*)(Ab + 8 * EMB);
            a[m][2] = *(const unsigned*)(Ab + 8);
            a[m][3] = *(const unsigned*)(Ab + 8 * EMB + 8);
        }
        #pragma unroll
        for (int n = 0; n < 8; n++) {
            const __half* Bb = W1 + (size_t)(C0 + n * 8 + r) * EMB + k0 + c2;
            unsigned b0 = *(const unsigned*)Bb;
            unsigned b1v = *(const unsigned*)(Bb + 8);
            mma16816(acc[0][n], a[0], b0, b1v);
            mma16816(acc[1][n], a[1], b0, b1v);
        }
    }

    // bias + relu + store H to smem (fp16)
    #pragma unroll
    for (int m = 0; m < 2; m++) {
        const int lr = rg * 32 + m * 16 + r;
        #pragma unroll
        for (int n = 0; n < 8; n++) {
            const int col = C0 + n * 8 + c2;
            float2 bv = *(const float2*)(B1 + col);
            __half2 h0 = __floats2half2_rn(fmaxf(acc[m][n][0] + bv.x, 0.0f),
                                           fmaxf(acc[m][n][1] + bv.y, 0.0f));
            __half2 h1 = __floats2half2_rn(fmaxf(acc[m][n][2] + bv.x, 0.0f),
                                           fmaxf(acc[m][n][3] + bv.y, 0.0f));
            *(unsigned*)(sH + lr * SH_PITCH + col)       = *(unsigned*)&h0;
            *(unsigned*)(sH + (lr + 8) * SH_PITCH + col) = *(unsigned*)&h1;
        }
    }
    __syncthreads();

    // ---- stage 2: acc = H @ W2 ----
    #pragma unroll
    for (int m = 0; m < 2; m++)
        #pragma unroll
        for (int n = 0; n < 8; n++)
            #pragma unroll
            for (int q = 0; q < 4; q++) acc[m][n][q] = 0.0f;

    #pragma unroll
    for (int kt = 0; kt < HID / 16; kt++) {
        const int k0 = kt * 16;
        unsigned a[2][4];
        #pragma unroll
        for (int m = 0; m < 2; m++) {
            const __half* Ab = sH + (rg * 32 + m * 16 + r) * SH_PITCH + k0 + c2;
            a[m][0] = *(const unsigned*)Ab;
            a[m][1] = *(const unsigned*)(Ab + 8 * SH_PITCH);
            a[m][2] = *(const unsigned*)(Ab + 8);
            a[m][3] = *(const unsigned*)(Ab + 8 * SH_PITCH + 8);
        }
        #pragma unroll
        for (int n = 0; n < 8; n++) {
            const __half* Bb = W2 + (size_t)(C0 + n * 8 + r) * HID + k0 + c2;
            unsigned b0 = *(const unsigned*)Bb;
            unsigned b1v = *(const unsigned*)(Bb + 8);
            mma16816(acc[0][n], a[0], b0, b1v);
            mma16816(acc[1][n], a[1], b0, b1v);
        }
    }

    // bias + fp16 store to g_lat
    #pragma unroll
    for (int m = 0; m < 2; m++) {
        const int row0 = R0 + m * 16 + r;
        #pragma unroll
        for (int n = 0; n < 8; n++) {
            const int col = C0 + n * 8 + c2;
            float2 bv = *(const float2*)(B2 + col);
            __half2 h0 = __floats2half2_rn(acc[m][n][0] + bv.x, acc[m][n][1] + bv.y);
            __half2 h1 = __floats2half2_rn(acc[m][n][2] + bv.x, acc[m][n][3] + bv.y);
            *(unsigned*)(g_lat + (size_t)row0 * 256 + branch * 128 + col)       = *(unsigned*)&h0;
            *(unsigned*)(g_lat + (size_t)(row0 + 8) * 256 + branch * 128 + col) = *(unsigned*)&h1;
        }
    }
}

// ---------------------------------------------------------------------------
// Edge kernel: one warp per (i,j) pair, no smem, no block sync.
// Lanes 0-15 accumulate the link dot, lanes 16-31 the aa dot.
// aa/fdiff gathers issued BEFORE latent loads to overlap DRAM latency.
// ---------------------------------------------------------------------------
__device__ __forceinline__ float fsigmoid(float x) {
    return 1.0f / (1.0f + __expf(-x));
}

__global__ __launch_bounds__(256) void edge_kernel(
    const float* __restrict__ aa,
    const float* __restrict__ fdiff,
    const int*   __restrict__ pos_e,
    const int*   __restrict__ neg_e,
    const int*   __restrict__ pot_e,
    const float* __restrict__ emb_w,
    const float* __restrict__ struct_w,
    float* __restrict__ out)
{
    const int b    = blockIdx.x;
    const int wib  = threadIdx.x >> 5;
    const int lane = threadIdx.x & 31;
    const int gw   = b * 8 + wib;

    int i, j;
    if (b < NEG_BLKS) {
        i = neg_e[gw]; j = neg_e[ENEG + gw];
    } else if (b < POSNEG_BLKS) {
        int le = gw - ENEG;
        i = pos_e[le]; j = pos_e[EPOS + le];
    } else {
        int le = gw - (ENEG + EPOS);
        i = pot_e[le]; j = pot_e[EPOT + le];
    }

    // early gathers (lane 0 only) — overlap DRAM latency with the dots
    float aval = 0.0f, fdv = 0.0f;
    if (lane == 0) {
        aval = __ldg(aa + (size_t)i * Nn + j);
        if (b < POSNEG_BLKS) fdv = __ldg(fdiff + (size_t)i * Nn + j);
    }

    // each lane: 8 halves (16B) of the combined [link|aa] node row
    const uint4 u = *((const uint4*)(g_lat + (size_t)i * 256) + lane);
    const uint4 v = *((const uint4*)(g_lat + (size_t)j * 256) + lane);

    float d = 0.0f;
    {
        float2 a, c;
        a = __half22float2(*(const __half2*)&u.x); c = __half22float2(*(const __half2*)&v.x);
        d += a.x * c.x + a.y * c.y;
        a = __half22float2(*(const __half2*)&u.y); c = __half22float2(*(const __half2*)&v.y);
        d += a.x * c.x + a.y * c.y;
        a = __half22float2(*(const __half2*)&u.z); c = __half22float2(*(const __half2*)&v.z);
        d += a.x * c.x + a.y * c.y;
        a = __half22float2(*(const __half2*)&u.w); c = __half22float2(*(const __half2*)&v.w);
        d += a.x * c.x + a.y * c.y;
    }
    #pragma unroll
    for (int s = 8; s; s >>= 1)
        d += __shfl_xor_sync(0xffffffffu, d, s);
    float dother = __shfl_xor_sync(0xffffffffu, d, 16);

    if (lane == 0) {
        float ew = emb_w[0], sw = struct_w[0];
        float lc = fsigmoid(d);
        float ac = fsigmoid(dother * aval);
        float vv = fsigmoid(ew * lc + sw * ac);
        if (b >= POSNEG_BLKS) {
            out[1 + gw - (ENEG + EPOS)] = (vv < TDEL) ? 0.0f : vv;
        } else {
            float fd = fdv * (1.0f / SIGMA);
            float q = fd * fd;
            float contrib;
            if (b >= NEG_BLKS) {             // positive edge
                float e1 = vv - 1.0f;
                contrib = __expf(-q) * e1 * e1;
            } else {                          // negative edge
                contrib = __expf(q) * vv * vv;
            }
            atomicAdd(&g_loss[(gw & 63) * 32], contrib);   // no-return -> REDG
        }
    }
}

__global__ void finalize_kernel(float* __restrict__ out) {
    if (threadIdx.x == 0) {
        float s = 0.0f;
        #pragma unroll
        for (int t = 0; t < 64; t++) s += g_loss[t * 32];
        out[0] = s * ((float)Nn / (float)(ENEG + EPOS));
    }
}

// ---------------------------------------------------------------------------
extern "C" void kernel_launch(void* const* d_in, const int* in_sizes, int n_in,
                              void* d_out, int out_size)
{
    const float* emb   = (const float*)d_in[0];
    const float* aa    = (const float*)d_in[1];
    const float* fdiff = (const float*)d_in[2];
    const float* W1l   = (const float*)d_in[3];
    const float* b1l   = (const float*)d_in[4];
    const float* W2l   = (const float*)d_in[5];
    const float* b2l   = (const float*)d_in[6];
    const float* W1a   = (const float*)d_in[7];
    const float* b1a   = (const float*)d_in[8];
    const float* W2a   = (const float*)d_in[9];
    const float* b2a   = (const float*)d_in[10];
    const float* emw   = (const float*)d_in[11];
    const float* stw   = (const float*)d_in[12];
    const int*   pose  = (const int*)d_in[13];
    const int*   nege  = (const int*)d_in[14];
    const int*   pote  = (const int*)d_in[15];
    float* out = (float*)d_out;

    prep_kernel<<<Nn + 384, 256>>>(emb, W1l, W1a, W2l, W2a);

    dim3 mgrid(Nn / 64, 2);
    mlp_kernel<<<mgrid, 128>>>(b1l, b2l, b1a, b2a);

    const int TOT = ENEG + EPOS + EPOT;          // 385024
    edge_kernel<<<TOT / 8, 256>>>(aa, fdiff, pose, nege, pote, emw, stw, out);

    finalize_kernel<<<1, 32>>>(out);
}

// round 5
// speedup vs baseline: 1.4390x; 1.1603x over previous
#include <cuda_runtime.h>
#include <cuda_fp16.h>

#define Nn    6144
#define EMB   256
#define HID   128
#define EPOS  98304
#define ENEG  24576
#define EPOT  262144
#define SIGMA 100.0f
#define TDEL  0.1f

#define TOT       (ENEG + EPOS + EPOT)   // 385024
#define EDGE_BLKS (TOT / 16)             // 24064 (16 edges per block)
#define NEG_B2    (ENEG / 16)            // 1536
#define PN_B2     ((ENEG + EPOS) / 16)   // 7680

// fp16 staging
__device__ __half hE[Nn * EMB];            // emb, row-major
__device__ __half hW1t[2][HID * EMB];      // n-major: [n*256 + k]
__device__ __half hW2t[2][HID * HID];      // n-major: [n*128 + k]
// latents: per node [link 0..127 | aa 128..255] = 512B
__device__ __half g_lat[Nn * 256];
// spread loss accumulators (128B stride) + completion ticket
__device__ float g_loss[64 * 32];
__device__ unsigned g_done;

// ---------------------------------------------------------------------------
// prep: fp32 -> fp16 conversions + weight transpose + loss zeroing
// ---------------------------------------------------------------------------
__global__ __launch_bounds__(256) void prep_kernel(
    const float* __restrict__ emb,
    const float* __restrict__ W1l, const float* __restrict__ W1a,
    const float* __restrict__ W2l, const float* __restrict__ W2a)
{
    const int b = blockIdx.x, tid = threadIdx.x;
    if (b == 0 && tid < 64) g_loss[tid * 32] = 0.0f;
    if (b == 1 && tid == 0) g_done = 0;
    if (b < Nn) {
        int idx = b * EMB + tid;
        hE[idx] = __float2half(emb[idx]);
    } else {
        int widx = (b - Nn) * 256 + tid;          // [0, 98304)
        if (widx < 2 * EMB * HID) {               // W1 transposes
            int br = widx >> 15;
            int t  = widx & 32767;
            int k  = t >> 7, n = t & 127;
            const float* W = br ? W1a : W1l;
            hW1t[br][n * EMB + k] = __float2half(W[k * HID + n]);
        } else {
            int t2 = widx - 2 * EMB * HID;
            int br = t2 >> 14;
            int t  = t2 & 16383;
            int k  = t >> 7, n = t & 127;
            const float* W = br ? W2a : W2l;
            hW2t[br][n * HID + k] = __float2half(W[k * HID + n]);
        }
    }
}

// ---------------------------------------------------------------------------
// MLP via mma.sync.m16n8k16 (HMMA, fp16 in / fp32 accum).
// Block: 128 threads = 4 warps. Block tile: 64 rows x 128 cols.
// ---------------------------------------------------------------------------
__device__ __forceinline__ void mma16816(float* c, const unsigned* a,
                                         unsigned b0, unsigned b1) {
    asm volatile(
        "mma.sync.aligned.m16n8k16.row.col.f32.f16.f16.f32 "
        "{%0,%1,%2,%3}, {%4,%5,%6,%7}, {%8,%9}, {%0,%1,%2,%3};"
        : "+f"(c[0]), "+f"(c[1]), "+f"(c[2]), "+f"(c[3])
        : "r"(a[0]), "r"(a[1]), "r"(a[2]), "r"(a[3]), "r"(b0), "r"(b1));
}

#define SH_PITCH 136

__global__ __launch_bounds__(128) void mlp_kernel(
    const float* __restrict__ b1l, const float* __restrict__ b2l,
    const float* __restrict__ b1a, const float* __restrict__ b2a)
{
    __shared__ __half sH[64 * SH_PITCH];

    const int branch = blockIdx.y;
    const float* B1 = branch ? b1a : b1l;
    const float* B2 = branch ? b2a : b2l;
    const __half* W1 = hW1t[branch];
    const __half* W2 = hW2t[branch];

    const int tid  = threadIdx.x;
    const int w    = tid >> 5;
    const int lane = tid & 31;
    const int rg   = w & 1;
    const int cg   = w >> 1;
    const int r    = lane >> 2;
    const int c2   = (lane & 3) * 2;

    const int R0 = blockIdx.x * 64 + rg * 32;
    const int C0 = cg * 64;

    float acc[2][8][4];
    #pragma unroll
    for (int m = 0; m < 2; m++)
        #pragma unroll
        for (int n = 0; n < 8; n++)
            #pragma unroll
            for (int q = 0; q < 4; q++) acc[m][n][q] = 0.0f;

    // ---- stage 1: acc = emb @ W1 ----
    #pragma unroll 4
    for (int kt = 0; kt < EMB / 16; kt++) {
        const int k0 = kt * 16;
        unsigned a[2][4];
        #pragma unroll
        for (int m = 0; m < 2; m++) {
            const __half* Ab = hE + (size_t)(R0 + m * 16 + r) * EMB + k0 + c2;
            a[m][0] = *(const unsigned*)Ab;
            a[m][1] = *(const unsigned*)(Ab + 8 * EMB);
            a[m][2] = *(const unsigned*)(Ab + 8);
            a[m][3] = *(const unsigned*)(Ab + 8 * EMB + 8);
        }
        #pragma unroll
        for (int n = 0; n < 8; n++) {
            const __half* Bb = W1 + (size_t)(C0 + n * 8 + r) * EMB + k0 + c2;
            unsigned b0 = *(const unsigned*)Bb;
            unsigned b1v = *(const unsigned*)(Bb + 8);
            mma16816(acc[0][n], a[0], b0, b1v);
            mma16816(acc[1][n], a[1], b0, b1v);
        }
    }

    #pragma unroll
    for (int m = 0; m < 2; m++) {
        const int lr = rg * 32 + m * 16 + r;
        #pragma unroll
        for (int n = 0; n < 8; n++) {
            const int col = C0 + n * 8 + c2;
            float2 bv = *(const float2*)(B1 + col);
            __half2 h0 = __floats2half2_rn(fmaxf(acc[m][n][0] + bv.x, 0.0f),
                                           fmaxf(acc[m][n][1] + bv.y, 0.0f));
            __half2 h1 = __floats2half2_rn(fmaxf(acc[m][n][2] + bv.x, 0.0f),
                                           fmaxf(acc[m][n][3] + bv.y, 0.0f));
            *(unsigned*)(sH + lr * SH_PITCH + col)       = *(unsigned*)&h0;
            *(unsigned*)(sH + (lr + 8) * SH_PITCH + col) = *(unsigned*)&h1;
        }
    }
    __syncthreads();

    // ---- stage 2: acc = H @ W2 ----
    #pragma unroll
    for (int m = 0; m < 2; m++)
        #pragma unroll
        for (int n = 0; n < 8; n++)
            #pragma unroll
            for (int q = 0; q < 4; q++) acc[m][n][q] = 0.0f;

    #pragma unroll
    for (int kt = 0; kt < HID / 16; kt++) {
        const int k0 = kt * 16;
        unsigned a[2][4];
        #pragma unroll
        for (int m = 0; m < 2; m++) {
            const __half* Ab = sH + (rg * 32 + m * 16 + r) * SH_PITCH + k0 + c2;
            a[m][0] = *(const unsigned*)Ab;
            a[m][1] = *(const unsigned*)(Ab + 8 * SH_PITCH);
            a[m][2] = *(const unsigned*)(Ab + 8);
            a[m][3] = *(const unsigned*)(Ab + 8 * SH_PITCH + 8);
        }
        #pragma unroll
        for (int n = 0; n < 8; n++) {
            const __half* Bb = W2 + (size_t)(C0 + n * 8 + r) * HID + k0 + c2;
            unsigned b0 = *(const unsigned*)Bb;
            unsigned b1v = *(const unsigned*)(Bb + 8);
            mma16816(acc[0][n], a[0], b0, b1v);
            mma16816(acc[1][n], a[1], b0, b1v);
        }
    }

    #pragma unroll
    for (int m = 0; m < 2; m++) {
        const int row0 = R0 + m * 16 + r;
        #pragma unroll
        for (int n = 0; n < 8; n++) {
            const int col = C0 + n * 8 + c2;
            float2 bv = *(const float2*)(B2 + col);
            __half2 h0 = __floats2half2_rn(acc[m][n][0] + bv.x, acc[m][n][1] + bv.y);
            __half2 h1 = __floats2half2_rn(acc[m][n][2] + bv.x, acc[m][n][3] + bv.y);
            *(unsigned*)(g_lat + (size_t)row0 * 256 + branch * 128 + col)       = *(unsigned*)&h0;
            *(unsigned*)(g_lat + (size_t)(row0 + 8) * 256 + branch * 128 + col) = *(unsigned*)&h1;
        }
    }
}

// ---------------------------------------------------------------------------
// Edge kernel: TWO edges per warp (16-lane groups), 16 edges per block.
// Within each 16-lane group: lanes s=0..7 cover the link half (256B),
// lanes s=8..15 the aa half. 3+1 shfl levels instead of 5+1.
// Last block folds the finalize reduction (ticket pattern).
// ---------------------------------------------------------------------------
__device__ __forceinline__ float fsigmoid(float x) {
    return 1.0f / (1.0f + __expf(-x));
}

__device__ __forceinline__ float dot16h(uint4 u, uint4 v) {
    float d = 0.0f;
    float2 a, c;
    a = __half22float2(*(const __half2*)&u.x); c = __half22float2(*(const __half2*)&v.x);
    d += a.x * c.x + a.y * c.y;
    a = __half22float2(*(const __half2*)&u.y); c = __half22float2(*(const __half2*)&v.y);
    d += a.x * c.x + a.y * c.y;
    a = __half22float2(*(const __half2*)&u.z); c = __half22float2(*(const __half2*)&v.z);
    d += a.x * c.x + a.y * c.y;
    a = __half22float2(*(const __half2*)&u.w); c = __half22float2(*(const __half2*)&v.w);
    d += a.x * c.x + a.y * c.y;
    return d;
}

__global__ __launch_bounds__(256) void edge_kernel(
    const float* __restrict__ aa,
    const float* __restrict__ fdiff,
    const int*   __restrict__ pos_e,
    const int*   __restrict__ neg_e,
    const int*   __restrict__ pot_e,
    const float* __restrict__ emb_w,
    const float* __restrict__ struct_w,
    float* __restrict__ out)
{
    const int b    = blockIdx.x;
    const int tid  = threadIdx.x;
    const int warp = tid >> 5;
    const int lane = tid & 31;
    const int h    = lane >> 4;       // which edge of the pair
    const int s    = lane & 15;       // sub-lane within the 16-lane group
    const int e    = b * 16 + warp * 2 + h;

    int i, j;
    if (b < NEG_B2) {
        i = neg_e[e]; j = neg_e[ENEG + e];
    } else if (b < PN_B2) {
        int le = e - ENEG;
        i = pos_e[le]; j = pos_e[EPOS + le];
    } else {
        int le = e - (ENEG + EPOS);
        i = pot_e[le]; j = pot_e[EPOT + le];
    }

    // early DRAM gathers by the leader lane of each group — overlap with dots
    float aval = 0.0f, fdv = 0.0f;
    if (s == 0) {
        aval = __ldg(aa + (size_t)i * Nn + j);
        if (b < PN_B2) fdv = __ldg(fdiff + (size_t)i * Nn + j);
    }

    // each lane: 32B from i-row and 32B from j-row (coalesced 512B per group)
    const uint4* Ri = (const uint4*)(g_lat + (size_t)i * 256);
    const uint4* Rj = (const uint4*)(g_lat + (size_t)j * 256);
    uint4 u0 = Ri[2 * s],     v0 = Rj[2 * s];
    uint4 u1 = Ri[2 * s + 1], v1 = Rj[2 * s + 1];

    float d = dot16h(u0, v0) + dot16h(u1, v1);

    // reduce within each 8-lane sub-group (link: s 0-7, aa: s 8-15)
    d += __shfl_xor_sync(0xffffffffu, d, 1);
    d += __shfl_xor_sync(0xffffffffu, d, 2);
    d += __shfl_xor_sync(0xffffffffu, d, 4);
    float dother = __shfl_xor_sync(0xffffffffu, d, 8);   // leader gets aa-dot

    if (s == 0) {
        float ew = emb_w[0], sw = struct_w[0];
        float lc = fsigmoid(d);
        float ac = fsigmoid(dother * aval);
        float vv = fsigmoid(ew * lc + sw * ac);
        if (b >= PN_B2) {
            out[1 + e - (ENEG + EPOS)] = (vv < TDEL) ? 0.0f : vv;
        } else {
            float fd = fdv * (1.0f / SIGMA);
            float q = fd * fd;
            float contrib;
            if (b >= NEG_B2) {               // positive edge
                float e1 = vv - 1.0f;
                contrib = __expf(-q) * e1 * e1;
            } else {                          // negative edge
                contrib = __expf(q) * vv * vv;
            }
            atomicAdd(&g_loss[(e & 63) * 32], contrib);
            __threadfence();                  // make REDG device-visible
        }
    }

    // ---- folded finalize: last block to retire does the reduction ----
    __syncthreads();
    if (tid == 0) {
        unsigned t = atomicAdd(&g_done, 1u);
        if (t == (unsigned)(EDGE_BLKS - 1)) {
            __threadfence();
            float sum = 0.0f;
            #pragma unroll
            for (int q = 0; q < 64; q++) sum += g_loss[q * 32];
            out[0] = sum * ((float)Nn / (float)(ENEG + EPOS));
            g_done = 0;                      // reset for next graph replay
        }
    }
}

// ---------------------------------------------------------------------------
extern "C" void kernel_launch(void* const* d_in, const int* in_sizes, int n_in,
                              void* d_out, int out_size)
{
    const float* emb   = (const float*)d_in[0];
    const float* aa    = (const float*)d_in[1];
    const float* fdiff = (const float*)d_in[2];
    const float* W1l   = (const float*)d_in[3];
    const float* b1l   = (const float*)d_in[4];
    const float* W2l   = (const float*)d_in[5];
    const float* b2l   = (const float*)d_in[6];
    const float* W1a   = (const float*)d_in[7];
    const float* b1a   = (const float*)d_in[8];
    const float* W2a   = (const float*)d_in[9];
    const float* b2a   = (const float*)d_in[10];
    const float* emw   = (const float*)d_in[11];
    const float* stw   = (const float*)d_in[12];
    const int*   pose  = (const int*)d_in[13];
    const int*   nege  = (const int*)d_in[14];
    const int*   pote  = (const int*)d_in[15];
    float* out = (float*)d_out;

    prep_kernel<<<Nn + 384, 256>>>(emb, W1l, W1a, W2l, W2a);

    dim3 mgrid(Nn / 64, 2);
    mlp_kernel<<<mgrid, 128>>>(b1l, b2l, b1a, b2a);

    edge_kernel<<<EDGE_BLKS, 256>>>(aa, fdiff, pose, nege, pote, emw, stw, out);
}